// round 6
// baseline (speedup 1.0000x reference)
#include <cuda_runtime.h>
#include <cuda_fp16.h>
#include <cuda_fp8.h>
#include <stdint.h>

#define BZ 8
#define TT 2048
#define FT 512
#define HD 512
#define MTOT (BZ * TT)   // 16384

#define LUP  4096.0f            // 2^12
#define FOLD 0.000244140625f    // 2^-12

// ---------------- scratch (device globals; allocation-free) ----------------
__device__ __align__(16) __half g_qh[MTOT * FT], g_kh[MTOT * FT], g_vh[MTOT * FT];
__device__ __align__(16) unsigned char g_q8[(size_t)MTOT * 2 * FT], g_k8[(size_t)MTOT * 2 * FT],
                                       g_v8[(size_t)MTOT * 2 * FT];
__device__ __align__(16) __half g_Wqh[FT * HD], g_Wkh[FT * HD], g_Wvh[FT * HD];
__device__ __align__(16) unsigned char g_Wq8[FT * 2 * HD], g_Wk8[FT * 2 * HD], g_Wv8[FT * 2 * HD];
__device__ __align__(16) __half g_Qh[MTOT * HD], g_Kh[MTOT * HD];
__device__ __align__(16) unsigned char g_Q8[(size_t)MTOT * 2 * HD], g_K8[(size_t)MTOT * 2 * HD];
__device__ __align__(16) __half g_Vh[MTOT * HD], g_Vl[MTOT * HD];
__device__ __align__(16) __half g_Vth[(size_t)BZ * HD * TT];
__device__ __align__(16) unsigned char g_Vt8[(size_t)BZ * HD * 2 * TT];
__device__ __align__(16) float g_S[(size_t)BZ * TT * TT];
__device__ __align__(16) __half g_Ph[(size_t)BZ * TT * TT];
__device__ __align__(16) unsigned char g_P8[(size_t)BZ * TT * 2 * TT];

// ---------------- helpers ----------------
__device__ __forceinline__ uint32_t smem_u32(const void* p) {
    uint32_t a;
    asm("{ .reg .u64 t; cvta.to.shared.u64 t, %1; cvt.u32.u64 %0, t; }" : "=r"(a) : "l"(p));
    return a;
}
__device__ __forceinline__ unsigned char f2fp8(float x) {
    return (unsigned char)__nv_cvt_float_to_fp8(x, __NV_SATFINITE, __NV_E4M3);
}

#define CP16(dst, src) \
    asm volatile("cp.async.cg.shared.global [%0], [%1], 16;" :: "r"(dst), "l"(src) : "memory")

#define LDSM4(r, addr) \
    asm volatile("ldmatrix.sync.aligned.m8n8.x4.shared.b16 {%0,%1,%2,%3}, [%4];" \
                 : "=r"((r)[0]), "=r"((r)[1]), "=r"((r)[2]), "=r"((r)[3]) : "r"(addr))

#define MMAF16(d, a, b0, b1) \
    asm volatile("mma.sync.aligned.m16n8k16.row.col.f32.f16.f16.f32 " \
                 "{%0,%1,%2,%3}, {%4,%5,%6,%7}, {%8,%9}, {%0,%1,%2,%3};" \
                 : "+f"((d)[0]), "+f"((d)[1]), "+f"((d)[2]), "+f"((d)[3]) \
                 : "r"((a)[0]), "r"((a)[1]), "r"((a)[2]), "r"((a)[3]), "r"(b0), "r"(b1))

#define MMAFP8(t0, t1, t2, t3, a, b0, b1) \
    asm volatile("mma.sync.aligned.m16n8k32.row.col.f32.e4m3.e4m3.f32 " \
                 "{%0,%1,%2,%3}, {%4,%5,%6,%7}, {%8,%9}, {%0,%1,%2,%3};" \
                 : "+f"(t0), "+f"(t1), "+f"(t2), "+f"(t3) \
                 : "r"((a)[0]), "r"((a)[1]), "r"((a)[2]), "r"((a)[3]), "r"(b0), "r"(b1))

// ---------------- warp-MMA GEMM ----------------
// D[m,n] = sum_k A[m,k]*B[n,k].
// Main term: fp16 hi x fp16 hi (1 MMA/k16). Cross terms: one e4m3 k32 MMA over
// packed [fp8(Ah)|fp8(Al*2^12)] x [fp8(Bl*2^12)|fp8(Bh)], folded * 2^-12.
// Hi tile and packed tile have IDENTICAL byte strides -> identical addressing.
// MODE 0: out = (acc+bias)*scale -> fp16 hi + packed fp8 (pkOffH: 0=A-role,16=B-role)
// MODE 1: out = acc -> fp32 (batched)
// MODE 2: out = (acc+bias)*scale -> fp16 hi + fp16 lo
static constexpr int TILE_B = 16384;            // 128 rows x 128 bytes
static constexpr int STAGE_B = 4 * TILE_B;      // Ah, A8, Bh, B8 = 64 KB
static constexpr int GEMM_SMEM = 2 * STAGE_B;   // 128 KB

__device__ __forceinline__ void load_tile(uint32_t dstbase, const char* src, int ldB, int tid)
{
    #pragma unroll
    for (int j = 0; j < 4; j++) {
        const int seg = tid + j * 256;          // 1024 segs of 16B
        const int row = seg >> 3;               // 0..127
        const int colb = (seg & 7) * 16;        // 0..112
        const uint32_t off = (uint32_t)(row * 128 + colb);
        const uint32_t sw = off ^ ((off >> 3) & 0x70);
        CP16(dstbase + sw, src + (long)row * ldB + colb);
    }
}

template <int MODE>
__global__ __launch_bounds__(256, 1)
void gemm_mma(const char* __restrict__ Ahb, const char* __restrict__ A8b,
              const char* __restrict__ Bhb, const char* __restrict__ B8b,
              int ldaB, int ldbB, long sAB, long sBB, int K,
              const float* __restrict__ bias, float scale,
              float* __restrict__ outF, __half* __restrict__ outH,
              __half* __restrict__ outL, unsigned char* __restrict__ out8,
              int ldo, long sO, int pkOffH)
{
    extern __shared__ char smem[];
    const uint32_t sbase = smem_u32(smem);
    const int tid = threadIdx.x;
    const int wid = tid >> 5;
    const int L = tid & 31;
    const int bm = blockIdx.y * 128;
    const int bn = blockIdx.x * 128;
    const int wm = wid & 1;
    const int wn = wid >> 1;

    const char* pAh = Ahb + blockIdx.z * sAB + (long)bm * ldaB;
    const char* pA8 = A8b + blockIdx.z * sAB + (long)bm * ldaB;
    const char* pBh = Bhb + blockIdx.z * sBB + (long)bn * ldbB;
    const char* pB8 = B8b + blockIdx.z * sBB + (long)bn * ldbB;

    const int lr = L & 15;
    const int lc = (L >> 4) * 16;
    uint32_t aoffu[4], apat[4], boffu[2], bpat[2];
    #pragma unroll
    for (int mt = 0; mt < 4; mt++) {
        const uint32_t off = (uint32_t)((wm * 64 + mt * 16 + lr) * 128 + lc);
        aoffu[mt] = off;
        apat[mt] = (off >> 3) & 0x70;
    }
    #pragma unroll
    for (int ng = 0; ng < 2; ng++) {
        const uint32_t off = (uint32_t)((wn * 32 + ng * 16 + lr) * 128 + lc);
        boffu[ng] = off;
        bpat[ng] = (off >> 3) & 0x70;
    }

    float acc[4][4][4];
    #pragma unroll
    for (int mt = 0; mt < 4; mt++)
        #pragma unroll
        for (int nt = 0; nt < 4; nt++)
            #pragma unroll
            for (int r = 0; r < 4; r++)
                acc[mt][nt][r] = 0.0f;

    const int nchunk = K / 64;

    load_tile(sbase + 0 * TILE_B, pAh, ldaB, tid);
    load_tile(sbase + 1 * TILE_B, pA8, ldaB, tid);
    load_tile(sbase + 2 * TILE_B, pBh, ldbB, tid);
    load_tile(sbase + 3 * TILE_B, pB8, ldbB, tid);
    asm volatile("cp.async.commit_group;" ::: "memory");

    for (int ck = 0; ck < nchunk; ck++) {
        const int buf = ck & 1;
        if (ck + 1 < nchunk) {
            const int kb = (ck + 1) * 128;   // byte offset (64 k * 2B; packed same)
            const uint32_t db = sbase + (buf ^ 1) * STAGE_B;
            load_tile(db + 0 * TILE_B, pAh + kb, ldaB, tid);
            load_tile(db + 1 * TILE_B, pA8 + kb, ldaB, tid);
            load_tile(db + 2 * TILE_B, pBh + kb, ldbB, tid);
            load_tile(db + 3 * TILE_B, pB8 + kb, ldbB, tid);
            asm volatile("cp.async.commit_group;" ::: "memory");
            asm volatile("cp.async.wait_group 1;" ::: "memory");
        } else {
            asm volatile("cp.async.wait_group 0;" ::: "memory");
        }
        __syncthreads();

        const uint32_t cb = sbase + buf * STAGE_B;
        #pragma unroll
        for (int kk = 0; kk < 4; kk++) {
            uint32_t ah[4][4], a8[4][4], bh[2][4], b8[2][4];
            #pragma unroll
            for (int mt = 0; mt < 4; mt++) {
                const uint32_t sw = (aoffu[mt] + kk * 32) ^ apat[mt];
                LDSM4(ah[mt], cb + 0 * TILE_B + sw);
                LDSM4(a8[mt], cb + 1 * TILE_B + sw);
            }
            #pragma unroll
            for (int ng = 0; ng < 2; ng++) {
                const uint32_t sw = (boffu[ng] + kk * 32) ^ bpat[ng];
                LDSM4(bh[ng], cb + 2 * TILE_B + sw);
                LDSM4(b8[ng], cb + 3 * TILE_B + sw);
            }
            #pragma unroll
            for (int mt = 0; mt < 4; mt++) {
                #pragma unroll
                for (int nt = 0; nt < 4; nt++) {
                    const int ng = nt >> 1, h = nt & 1;
                    MMAF16(acc[mt][nt], ah[mt], bh[ng][h], bh[ng][h + 2]);
                    float t0 = 0.f, t1 = 0.f, t2 = 0.f, t3 = 0.f;
                    MMAFP8(t0, t1, t2, t3, a8[mt], b8[ng][h], b8[ng][h + 2]);
                    acc[mt][nt][0] = fmaf(t0, FOLD, acc[mt][nt][0]);
                    acc[mt][nt][1] = fmaf(t1, FOLD, acc[mt][nt][1]);
                    acc[mt][nt][2] = fmaf(t2, FOLD, acc[mt][nt][2]);
                    acc[mt][nt][3] = fmaf(t3, FOLD, acc[mt][nt][3]);
                }
            }
        }
        __syncthreads();
    }

    // epilogue
    const int r0 = bm + wm * 64 + (L >> 2);
    const int c0 = bn + wn * 32 + (L & 3) * 2;
    #pragma unroll
    for (int mt = 0; mt < 4; mt++) {
        #pragma unroll
        for (int nt = 0; nt < 4; nt++) {
            const int row = r0 + mt * 16;
            const int col = c0 + nt * 8;
            if (MODE == 1) {
                float* po = outF + (size_t)blockIdx.z * sO;
                *reinterpret_cast<float2*>(po + (size_t)row * ldo + col) =
                    make_float2(acc[mt][nt][0], acc[mt][nt][1]);
                *reinterpret_cast<float2*>(po + (size_t)(row + 8) * ldo + col) =
                    make_float2(acc[mt][nt][2], acc[mt][nt][3]);
            } else {
                const float b0 = bias[col], b1 = bias[col + 1];
                float x0 = (acc[mt][nt][0] + b0) * scale;
                float x1 = (acc[mt][nt][1] + b1) * scale;
                float x2 = (acc[mt][nt][2] + b0) * scale;
                float x3 = (acc[mt][nt][3] + b1) * scale;
                __half h0 = __float2half_rn(x0), h1 = __float2half_rn(x1);
                __half h2 = __float2half_rn(x2), h3 = __float2half_rn(x3);
                float l0 = x0 - __half2float(h0), l1 = x1 - __half2float(h1);
                float l2 = x2 - __half2float(h2), l3 = x3 - __half2float(h3);
                __half2 hh;
                hh.x = h0; hh.y = h1;
                *reinterpret_cast<__half2*>(outH + (size_t)row * ldo + col) = hh;
                hh.x = h2; hh.y = h3;
                *reinterpret_cast<__half2*>(outH + (size_t)(row + 8) * ldo + col) = hh;
                if (MODE == 2) {
                    __half2 ll;
                    ll.x = __float2half_rn(l0); ll.y = __float2half_rn(l1);
                    *reinterpret_cast<__half2*>(outL + (size_t)row * ldo + col) = ll;
                    ll.x = __float2half_rn(l2); ll.y = __float2half_rn(l3);
                    *reinterpret_cast<__half2*>(outL + (size_t)(row + 8) * ldo + col) = ll;
                } else {
                    const int base = 32 * (col >> 4) + (col & 15);
                    unsigned char* p0 = out8 + (size_t)row * 2 * ldo + base;
                    unsigned char* p1 = out8 + (size_t)(row + 8) * 2 * ldo + base;
                    uint16_t hi0 = (uint16_t)f2fp8(x0) | ((uint16_t)f2fp8(x1) << 8);
                    uint16_t lo0 = (uint16_t)f2fp8(l0 * LUP) | ((uint16_t)f2fp8(l1 * LUP) << 8);
                    uint16_t hi1 = (uint16_t)f2fp8(x2) | ((uint16_t)f2fp8(x3) << 8);
                    uint16_t lo1 = (uint16_t)f2fp8(l2 * LUP) | ((uint16_t)f2fp8(l3 * LUP) << 8);
                    *reinterpret_cast<uint16_t*>(p0 + pkOffH) = hi0;
                    *reinterpret_cast<uint16_t*>(p0 + (16 - pkOffH)) = lo0;
                    *reinterpret_cast<uint16_t*>(p1 + pkOffH) = hi1;
                    *reinterpret_cast<uint16_t*>(p1 + (16 - pkOffH)) = lo1;
                }
            }
        }
    }
}

// ---------------- small kernels ----------------
// fp32 -> fp16 hi + A-role packed fp8 [h | l*2^12]
__global__ __launch_bounds__(256) void fsplit(const float* __restrict__ x,
                                              __half* __restrict__ h,
                                              unsigned char* __restrict__ p8)
{
    const int i = (blockIdx.x * 256 + threadIdx.x) * 4;
    float4 v = *reinterpret_cast<const float4*>(x + i);
    __half h0 = __float2half_rn(v.x), h1 = __float2half_rn(v.y);
    __half h2 = __float2half_rn(v.z), h3 = __float2half_rn(v.w);
    float l0 = v.x - __half2float(h0), l1 = v.y - __half2float(h1);
    float l2 = v.z - __half2float(h2), l3 = v.w - __half2float(h3);
    __half2 a;
    a.x = h0; a.y = h1; *reinterpret_cast<__half2*>(h + i) = a;
    a.x = h2; a.y = h3; *reinterpret_cast<__half2*>(h + i + 2) = a;
    const int row = i >> 9;          // /512
    const int k = i & 511;
    unsigned char* pr = p8 + (size_t)row * 1024 + 32 * (k >> 4) + (k & 15);
    uint32_t hi = (uint32_t)f2fp8(v.x) | ((uint32_t)f2fp8(v.y) << 8)
                | ((uint32_t)f2fp8(v.z) << 16) | ((uint32_t)f2fp8(v.w) << 24);
    uint32_t lo = (uint32_t)f2fp8(l0 * LUP) | ((uint32_t)f2fp8(l1 * LUP) << 8)
                | ((uint32_t)f2fp8(l2 * LUP) << 16) | ((uint32_t)f2fp8(l3 * LUP) << 24);
    *reinterpret_cast<uint32_t*>(pr) = hi;
    *reinterpret_cast<uint32_t*>(pr + 16) = lo;
}

// W [K=512, N=512] -> Wt fp16 [N, K] + B-role packed fp8 [l*2^12 | h]
__global__ __launch_bounds__(256) void wsplit(const float* __restrict__ W,
                                              __half* __restrict__ Wth,
                                              unsigned char* __restrict__ W8)
{
    __shared__ float t[32][33];
    const int n0 = blockIdx.x * 32, k0 = blockIdx.y * 32;
    const int tx = threadIdx.x & 31, ty = threadIdx.x >> 5;
    #pragma unroll
    for (int i = 0; i < 4; i++) {
        const int r = ty + i * 8;
        t[r][tx] = W[(size_t)(k0 + r) * HD + n0 + tx];
    }
    __syncthreads();
    #pragma unroll
    for (int i = 0; i < 4; i++) {
        const int r = ty + i * 8;          // n offset
        const float v = t[tx][r];
        const int n = n0 + r, k = k0 + tx;
        __half h = __float2half_rn(v);
        float l = v - __half2float(h);
        Wth[(size_t)n * FT + k] = h;
        unsigned char* pr = W8 + (size_t)n * 1024 + 32 * (k >> 4) + (k & 15);
        pr[0] = f2fp8(l * LUP);
        pr[16] = f2fp8(v);
    }
}

// V fp16 h/l [B*T, H] -> Vt fp16 [B][H][T] + B-role packed fp8
__global__ __launch_bounds__(256) void transpose_v(const __half* __restrict__ Vh,
                                                   const __half* __restrict__ Vl,
                                                   __half* __restrict__ Vth,
                                                   unsigned char* __restrict__ Vt8)
{
    __shared__ __half th[32][33], tl[32][33];
    const int b = blockIdx.z;
    const int h0 = blockIdx.x * 32, s0 = blockIdx.y * 32;
    const int tx = threadIdx.x & 31, ty = threadIdx.x >> 5;
    #pragma unroll
    for (int i = 0; i < 4; i++) {
        const int r = ty + i * 8;
        const size_t src = ((size_t)b * TT + s0 + r) * HD + h0 + tx;
        th[r][tx] = Vh[src];
        tl[r][tx] = Vl[src];
    }
    __syncthreads();
    #pragma unroll
    for (int i = 0; i < 4; i++) {
        const int r = ty + i * 8;          // h offset
        const int hh = h0 + r, s = s0 + tx;
        const float vh = __half2float(th[tx][r]);
        const float vl = __half2float(tl[tx][r]);
        Vth[((size_t)b * HD + hh) * TT + s] = th[tx][r];
        unsigned char* pr = Vt8 + ((size_t)b * HD + hh) * 2 * TT + 32 * (s >> 4) + (s & 15);
        pr[0] = f2fp8(vl * LUP);
        pr[16] = f2fp8(vh);
    }
}

// softmax over rows of 2048 -> P fp16 hi + A-role packed fp8
__global__ __launch_bounds__(256) void softmax_k(const float* __restrict__ S,
                                                 __half* __restrict__ Ph,
                                                 unsigned char* __restrict__ P8)
{
    const size_t off = (size_t)blockIdx.x * TT;
    const int tid = threadIdx.x;
    const float* p = S + off + tid * 8;
    float v[8];
    float4 a = *reinterpret_cast<const float4*>(p);
    float4 b = *reinterpret_cast<const float4*>(p + 4);
    v[0] = a.x; v[1] = a.y; v[2] = a.z; v[3] = a.w;
    v[4] = b.x; v[5] = b.y; v[6] = b.z; v[7] = b.w;

    __shared__ float red[8];
    float m = v[0];
    #pragma unroll
    for (int i = 1; i < 8; i++) m = fmaxf(m, v[i]);
    #pragma unroll
    for (int o = 16; o > 0; o >>= 1) m = fmaxf(m, __shfl_xor_sync(0xffffffffu, m, o));
    if ((tid & 31) == 0) red[tid >> 5] = m;
    __syncthreads();
    float M = red[0];
    #pragma unroll
    for (int i = 1; i < 8; i++) M = fmaxf(M, red[i]);
    __syncthreads();

    float s = 0.f;
    #pragma unroll
    for (int i = 0; i < 8; i++) { v[i] = __expf(v[i] - M); s += v[i]; }
    #pragma unroll
    for (int o = 16; o > 0; o >>= 1) s += __shfl_xor_sync(0xffffffffu, s, o);
    if ((tid & 31) == 0) red[tid >> 5] = s;
    __syncthreads();
    float tot = 0.f;
    #pragma unroll
    for (int i = 0; i < 8; i++) tot += red[i];
    const float inv = __fdividef(1.0f, tot);

    __half* ph = Ph + off + tid * 8;
    uint32_t hi[2], lo[2];
    #pragma unroll
    for (int g = 0; g < 2; g++) {
        float x0 = v[g * 4 + 0] * inv, x1 = v[g * 4 + 1] * inv;
        float x2 = v[g * 4 + 2] * inv, x3 = v[g * 4 + 3] * inv;
        __half h0 = __float2half_rn(x0), h1 = __float2half_rn(x1);
        __half h2 = __float2half_rn(x2), h3 = __float2half_rn(x3);
        __half2 hh;
        hh.x = h0; hh.y = h1; *reinterpret_cast<__half2*>(ph + g * 4) = hh;
        hh.x = h2; hh.y = h3; *reinterpret_cast<__half2*>(ph + g * 4 + 2) = hh;
        float l0 = x0 - __half2float(h0), l1 = x1 - __half2float(h1);
        float l2 = x2 - __half2float(h2), l3 = x3 - __half2float(h3);
        hi[g] = (uint32_t)f2fp8(x0) | ((uint32_t)f2fp8(x1) << 8)
              | ((uint32_t)f2fp8(x2) << 16) | ((uint32_t)f2fp8(x3) << 24);
        lo[g] = (uint32_t)f2fp8(l0 * LUP) | ((uint32_t)f2fp8(l1 * LUP) << 8)
              | ((uint32_t)f2fp8(l2 * LUP) << 16) | ((uint32_t)f2fp8(l3 * LUP) << 24);
    }
    const int srow = tid * 8;
    unsigned char* pr = P8 + (size_t)blockIdx.x * 2 * TT + 32 * (srow >> 4) + (srow & 15);
    *reinterpret_cast<uint32_t*>(pr) = hi[0];
    *reinterpret_cast<uint32_t*>(pr + 4) = hi[1];
    *reinterpret_cast<uint32_t*>(pr + 16) = lo[0];
    *reinterpret_cast<uint32_t*>(pr + 20) = lo[1];
}

// ---------------- launch ----------------
extern "C" void kernel_launch(void* const* d_in, const int* in_sizes, int n_in,
                              void* d_out, int out_size)
{
    const float* q  = (const float*)d_in[0];
    const float* k  = (const float*)d_in[1];
    const float* v  = (const float*)d_in[2];
    const float* Wq = (const float*)d_in[3];
    const float* bq = (const float*)d_in[4];
    const float* Wk = (const float*)d_in[5];
    const float* bk = (const float*)d_in[6];
    const float* Wv = (const float*)d_in[7];
    const float* bv = (const float*)d_in[8];
    float* out = (float*)d_out;

    __half *qh, *kh, *vh, *wqh, *wkh, *wvh, *Qh, *Kh, *Vh, *Vl, *Vth, *Ph;
    unsigned char *q8, *k8, *v8, *wq8, *wk8, *wv8, *Q8, *K8, *Vt8, *P8;
    float* S;
    cudaGetSymbolAddress((void**)&qh, g_qh);   cudaGetSymbolAddress((void**)&q8, g_q8);
    cudaGetSymbolAddress((void**)&kh, g_kh);   cudaGetSymbolAddress((void**)&k8, g_k8);
    cudaGetSymbolAddress((void**)&vh, g_vh);   cudaGetSymbolAddress((void**)&v8, g_v8);
    cudaGetSymbolAddress((void**)&wqh, g_Wqh); cudaGetSymbolAddress((void**)&wq8, g_Wq8);
    cudaGetSymbolAddress((void**)&wkh, g_Wkh); cudaGetSymbolAddress((void**)&wk8, g_Wk8);
    cudaGetSymbolAddress((void**)&wvh, g_Wvh); cudaGetSymbolAddress((void**)&wv8, g_Wv8);
    cudaGetSymbolAddress((void**)&Qh, g_Qh);   cudaGetSymbolAddress((void**)&Q8, g_Q8);
    cudaGetSymbolAddress((void**)&Kh, g_Kh);   cudaGetSymbolAddress((void**)&K8, g_K8);
    cudaGetSymbolAddress((void**)&Vh, g_Vh);   cudaGetSymbolAddress((void**)&Vl, g_Vl);
    cudaGetSymbolAddress((void**)&Vth, g_Vth); cudaGetSymbolAddress((void**)&Vt8, g_Vt8);
    cudaGetSymbolAddress((void**)&S, g_S);
    cudaGetSymbolAddress((void**)&Ph, g_Ph);   cudaGetSymbolAddress((void**)&P8, g_P8);

    cudaFuncSetAttribute(gemm_mma<0>, cudaFuncAttributeMaxDynamicSharedMemorySize, GEMM_SMEM);
    cudaFuncSetAttribute(gemm_mma<1>, cudaFuncAttributeMaxDynamicSharedMemorySize, GEMM_SMEM);
    cudaFuncSetAttribute(gemm_mma<2>, cudaFuncAttributeMaxDynamicSharedMemorySize, GEMM_SMEM);

    // 1) split inputs (A-role pack)
    fsplit<<<MTOT * FT / 1024, 256>>>(q, qh, q8);
    fsplit<<<MTOT * FT / 1024, 256>>>(k, kh, k8);
    fsplit<<<MTOT * FT / 1024, 256>>>(v, vh, v8);
    // 2) transpose+split weights (B-role pack)
    wsplit<<<dim3(16, 16), 256>>>(Wq, wqh, wq8);
    wsplit<<<dim3(16, 16), 256>>>(Wk, wkh, wk8);
    wsplit<<<dim3(16, 16), 256>>>(Wv, wvh, wv8);
    // 3) projections (scale 0.25 folded into Q). Q8 = A-role (pkOffH 0), K8 = B-role (16)
    dim3 gp(HD / 128, MTOT / 128, 1);
    gemm_mma<0><<<gp, 256, GEMM_SMEM>>>((const char*)qh, (const char*)q8,
                                        (const char*)wqh, (const char*)wq8,
                                        2 * FT, 2 * FT, 0, 0, FT,
                                        bq, 0.25f, nullptr, Qh, nullptr, Q8, HD, 0, 0);
    gemm_mma<0><<<gp, 256, GEMM_SMEM>>>((const char*)kh, (const char*)k8,
                                        (const char*)wkh, (const char*)wk8,
                                        2 * FT, 2 * FT, 0, 0, FT,
                                        bk, 1.0f, nullptr, Kh, nullptr, K8, HD, 0, 16);
    gemm_mma<2><<<gp, 256, GEMM_SMEM>>>((const char*)vh, (const char*)v8,
                                        (const char*)wvh, (const char*)wv8,
                                        2 * FT, 2 * FT, 0, 0, FT,
                                        bv, 1.0f, nullptr, Vh, Vl, nullptr, HD, 0, 0);
    // 4) transpose V (B-role pack along s)
    transpose_v<<<dim3(HD / 32, TT / 32, BZ), 256>>>(Vh, Vl, Vth, Vt8);
    // 5) energy S = (0.25 Q) K^T
    dim3 ge(TT / 128, TT / 128, BZ);
    gemm_mma<1><<<ge, 256, GEMM_SMEM>>>((const char*)Qh, (const char*)Q8,
                                        (const char*)Kh, (const char*)K8,
                                        2 * HD, 2 * HD,
                                        (long)TT * HD * 2, (long)TT * HD * 2, HD,
                                        nullptr, 1.0f, S, nullptr, nullptr, nullptr,
                                        TT, (long)TT * TT, 0);
    // 6) softmax -> P fp16 + A-role pack
    softmax_k<<<MTOT, 256>>>(S, Ph, P8);
    // 7) out = P V
    dim3 go(HD / 128, TT / 128, BZ);
    gemm_mma<1><<<go, 256, GEMM_SMEM>>>((const char*)Ph, (const char*)P8,
                                        (const char*)Vth, (const char*)Vt8,
                                        2 * TT, 2 * TT,
                                        (long)TT * TT * 2, (long)HD * TT * 2, TT,
                                        nullptr, 1.0f, out, nullptr, nullptr, nullptr,
                                        HD, (long)TT * HD, 0);
}

// round 7
// speedup vs baseline: 1.4925x; 1.4925x over previous
#include <cuda_runtime.h>
#include <cuda_fp16.h>
#include <stdint.h>

#define BZ 8
#define TT 2048
#define FT 512
#define HD 512
#define MTOT (BZ * TT)   // 16384

// ---------------- scratch (device globals; allocation-free) ----------------
__device__ __align__(16) __half g_qh[MTOT * FT], g_ql[MTOT * FT];
__device__ __align__(16) __half g_kh[MTOT * FT], g_kl[MTOT * FT];
__device__ __align__(16) __half g_vh[MTOT * FT], g_vl[MTOT * FT];
__device__ __align__(16) __half g_Wqh[FT * HD], g_Wql[FT * HD];
__device__ __align__(16) __half g_Wkh[FT * HD], g_Wkl[FT * HD];
__device__ __align__(16) __half g_Wvh[FT * HD], g_Wvl[FT * HD];
__device__ __align__(16) __half g_Qh[MTOT * HD], g_Ql[MTOT * HD];
__device__ __align__(16) __half g_Kh[MTOT * HD], g_Kl[MTOT * HD];
__device__ __align__(16) __half g_Vh[MTOT * HD], g_Vl[MTOT * HD];
__device__ __align__(16) __half g_Vth[(size_t)BZ * HD * TT], g_Vtl[(size_t)BZ * HD * TT];
__device__ __align__(16) float g_S[(size_t)BZ * TT * TT];
__device__ __align__(16) __half g_Ph[(size_t)BZ * TT * TT], g_Pl[(size_t)BZ * TT * TT];

// ---------------- helpers ----------------
__device__ __forceinline__ uint32_t smem_u32(const void* p) {
    uint32_t a;
    asm("{ .reg .u64 t; cvta.to.shared.u64 t, %1; cvt.u32.u64 %0, t; }" : "=r"(a) : "l"(p));
    return a;
}

#define CP16(dst, src) \
    asm volatile("cp.async.cg.shared.global [%0], [%1], 16;" :: "r"(dst), "l"(src) : "memory")

#define LDSM4(r, addr) \
    asm volatile("ldmatrix.sync.aligned.m8n8.x4.shared.b16 {%0,%1,%2,%3}, [%4];" \
                 : "=r"((r)[0]), "=r"((r)[1]), "=r"((r)[2]), "=r"((r)[3]) : "r"(addr))

// fp16 inputs, fp32 accumulator (main term)
#define MMAF32(d, a, b0, b1) \
    asm volatile("mma.sync.aligned.m16n8k16.row.col.f32.f16.f16.f32 " \
                 "{%0,%1,%2,%3}, {%4,%5,%6,%7}, {%8,%9}, {%0,%1,%2,%3};" \
                 : "+f"((d)[0]), "+f"((d)[1]), "+f"((d)[2]), "+f"((d)[3]) \
                 : "r"((a)[0]), "r"((a)[1]), "r"((a)[2]), "r"((a)[3]), "r"(b0), "r"(b1))

// fp16 inputs, fp16 accumulator (cross terms; values are 2^-12-scale corrections)
#define MMAF16(c0, c1, a, b0, b1) \
    asm volatile("mma.sync.aligned.m16n8k16.row.col.f16.f16.f16.f16 " \
                 "{%0,%1}, {%2,%3,%4,%5}, {%6,%7}, {%0,%1};" \
                 : "+r"(c0), "+r"(c1) \
                 : "r"((a)[0]), "r"((a)[1]), "r"((a)[2]), "r"((a)[3]), "r"(b0), "r"(b1))

// ---------------- warp-MMA GEMM ----------------
// D[m,n] = sum_k A[m,k]*B[n,k], fp16 split: Ah*Bh (f32 acc) + (Ah*Bl + Al*Bh) (f16 acc, drained)
// K-chunk 32 (64B rows, SW64 swizzle), double-buffered, 64KB smem, 2 CTAs/SM.
static constexpr int TILE_B = 8192;             // 128 rows x 64 bytes
static constexpr int STAGE_B = 4 * TILE_B;      // Ah, Al, Bh, Bl = 32 KB
static constexpr int GEMM_SMEM = 2 * STAGE_B;   // 64 KB

__device__ __forceinline__ void load_tile(uint32_t dstbase, const __half* src, int ld, int tid)
{
    #pragma unroll
    for (int j = 0; j < 2; j++) {
        const int seg = tid + j * 256;          // 512 segs of 16B
        const int row = seg >> 2;               // 0..127
        const int colb = (seg & 3) * 16;        // 0..48
        const uint32_t off = (uint32_t)(row * 64 + colb);
        const uint32_t sw = off ^ ((off >> 3) & 0x30);
        CP16(dstbase + sw, (const char*)src + (long)row * ld * 2 + colb);
    }
}

template <int MODE>
__global__ __launch_bounds__(256, 2)
void gemm_mma(const __half* __restrict__ Ah, const __half* __restrict__ Al,
              const __half* __restrict__ Bh, const __half* __restrict__ Bl,
              int lda, int ldb, long sA, long sB, int K,
              const float* __restrict__ bias, float scale,
              float* __restrict__ outF, __half* __restrict__ outH, __half* __restrict__ outL,
              int ldo, long sO)
{
    extern __shared__ char smem[];
    const uint32_t sbase = smem_u32(smem);
    const int tid = threadIdx.x;
    const int wid = tid >> 5;
    const int L = tid & 31;
    const int bm = blockIdx.y * 128;
    const int bn = blockIdx.x * 128;
    const int wm = wid & 1;       // 0..1  (64 rows each)
    const int wn = wid >> 1;      // 0..3  (32 cols each)

    const __half* pAh = Ah + (long)blockIdx.z * sA + (long)bm * lda;
    const __half* pAl = Al + (long)blockIdx.z * sA + (long)bm * lda;
    const __half* pBh = Bh + (long)blockIdx.z * sB + (long)bn * ldb;
    const __half* pBl = Bl + (long)blockIdx.z * sB + (long)bn * ldb;

    // ldmatrix lane offsets: unswizzled base + row-pure swizzle pattern.
    const int lr = L & 15;
    const int lc = (L >> 4) * 16;
    uint32_t aoffu[4], apat[4], boffu[2], bpat[2];
    #pragma unroll
    for (int mt = 0; mt < 4; mt++) {
        const uint32_t off = (uint32_t)((wm * 64 + mt * 16 + lr) * 64 + lc);
        aoffu[mt] = off;
        apat[mt] = (off >> 3) & 0x30;
    }
    #pragma unroll
    for (int ng = 0; ng < 2; ng++) {
        const uint32_t off = (uint32_t)((wn * 32 + ng * 16 + lr) * 64 + lc);
        boffu[ng] = off;
        bpat[ng] = (off >> 3) & 0x30;
    }

    float acc[4][4][4];
    #pragma unroll
    for (int mt = 0; mt < 4; mt++)
        #pragma unroll
        for (int nt = 0; nt < 4; nt++)
            #pragma unroll
            for (int r = 0; r < 4; r++)
                acc[mt][nt][r] = 0.0f;

    const int nchunk = K / 32;

    load_tile(sbase + 0 * TILE_B, pAh, lda, tid);
    load_tile(sbase + 1 * TILE_B, pAl, lda, tid);
    load_tile(sbase + 2 * TILE_B, pBh, ldb, tid);
    load_tile(sbase + 3 * TILE_B, pBl, ldb, tid);
    asm volatile("cp.async.commit_group;" ::: "memory");

    for (int ck = 0; ck < nchunk; ck++) {
        const int buf = ck & 1;
        if (ck + 1 < nchunk) {
            const int k0 = (ck + 1) * 32;
            const uint32_t db = sbase + (buf ^ 1) * STAGE_B;
            load_tile(db + 0 * TILE_B, pAh + k0, lda, tid);
            load_tile(db + 1 * TILE_B, pAl + k0, lda, tid);
            load_tile(db + 2 * TILE_B, pBh + k0, ldb, tid);
            load_tile(db + 3 * TILE_B, pBl + k0, ldb, tid);
            asm volatile("cp.async.commit_group;" ::: "memory");
            asm volatile("cp.async.wait_group 1;" ::: "memory");
        } else {
            asm volatile("cp.async.wait_group 0;" ::: "memory");
        }
        __syncthreads();

        const uint32_t cb = sbase + buf * STAGE_B;
        #pragma unroll
        for (int kk = 0; kk < 2; kk++) {
            uint32_t bh[2][4], bl[2][4];
            #pragma unroll
            for (int ng = 0; ng < 2; ng++) {
                const uint32_t sw = (boffu[ng] + kk * 32) ^ bpat[ng];
                LDSM4(bh[ng], cb + 2 * TILE_B + sw);
                LDSM4(bl[ng], cb + 3 * TILE_B + sw);
            }
            #pragma unroll
            for (int mt = 0; mt < 4; mt++) {
                uint32_t ah[4], al[4];
                const uint32_t sw = (aoffu[mt] + kk * 32) ^ apat[mt];
                LDSM4(ah, cb + 0 * TILE_B + sw);
                LDSM4(al, cb + 1 * TILE_B + sw);
                #pragma unroll
                for (int nt = 0; nt < 4; nt++) {
                    const int ng = nt >> 1, h = nt & 1;
                    const uint32_t b0h = bh[ng][h], b1h = bh[ng][h + 2];
                    const uint32_t b0l = bl[ng][h], b1l = bl[ng][h + 2];
                    MMAF32(acc[mt][nt], ah, b0h, b1h);
                    uint32_t c0 = 0u, c1 = 0u;
                    MMAF16(c0, c1, ah, b0l, b1l);
                    MMAF16(c0, c1, al, b0h, b1h);
                    const __half2 h20 = *reinterpret_cast<__half2*>(&c0);
                    const __half2 h21 = *reinterpret_cast<__half2*>(&c1);
                    const float2 f0 = __half22float2(h20);
                    const float2 f1 = __half22float2(h21);
                    acc[mt][nt][0] += f0.x;
                    acc[mt][nt][1] += f0.y;
                    acc[mt][nt][2] += f1.x;
                    acc[mt][nt][3] += f1.y;
                }
            }
        }
        __syncthreads();
    }

    // epilogue
    const int r0 = bm + wm * 64 + (L >> 2);
    const int c0 = bn + wn * 32 + (L & 3) * 2;
    #pragma unroll
    for (int mt = 0; mt < 4; mt++) {
        #pragma unroll
        for (int nt = 0; nt < 4; nt++) {
            const int row = r0 + mt * 16;
            const int col = c0 + nt * 8;
            if (MODE == 1) {
                float* po = outF + (size_t)blockIdx.z * sO;
                *reinterpret_cast<float2*>(po + (size_t)row * ldo + col) =
                    make_float2(acc[mt][nt][0], acc[mt][nt][1]);
                *reinterpret_cast<float2*>(po + (size_t)(row + 8) * ldo + col) =
                    make_float2(acc[mt][nt][2], acc[mt][nt][3]);
            } else {
                const float b0 = bias[col], b1 = bias[col + 1];
                float x0 = (acc[mt][nt][0] + b0) * scale;
                float x1 = (acc[mt][nt][1] + b1) * scale;
                float x2 = (acc[mt][nt][2] + b0) * scale;
                float x3 = (acc[mt][nt][3] + b1) * scale;
                __half h0 = __float2half_rn(x0), h1 = __float2half_rn(x1);
                __half h2 = __float2half_rn(x2), h3 = __float2half_rn(x3);
                __half l0 = __float2half_rn(x0 - __half2float(h0));
                __half l1 = __float2half_rn(x1 - __half2float(h1));
                __half l2 = __float2half_rn(x2 - __half2float(h2));
                __half l3 = __float2half_rn(x3 - __half2float(h3));
                __half2 t;
                t.x = h0; t.y = h1;
                *reinterpret_cast<__half2*>(outH + (size_t)row * ldo + col) = t;
                t.x = h2; t.y = h3;
                *reinterpret_cast<__half2*>(outH + (size_t)(row + 8) * ldo + col) = t;
                t.x = l0; t.y = l1;
                *reinterpret_cast<__half2*>(outL + (size_t)row * ldo + col) = t;
                t.x = l2; t.y = l3;
                *reinterpret_cast<__half2*>(outL + (size_t)(row + 8) * ldo + col) = t;
            }
        }
    }
}

// ---------------- small kernels ----------------
__global__ __launch_bounds__(256) void fsplit(const float* __restrict__ x,
                                              __half* __restrict__ h, __half* __restrict__ l)
{
    const int i = (blockIdx.x * 256 + threadIdx.x) * 4;
    float4 v = *reinterpret_cast<const float4*>(x + i);
    __half h0 = __float2half_rn(v.x), h1 = __float2half_rn(v.y);
    __half h2 = __float2half_rn(v.z), h3 = __float2half_rn(v.w);
    __half l0 = __float2half_rn(v.x - __half2float(h0));
    __half l1 = __float2half_rn(v.y - __half2float(h1));
    __half l2 = __float2half_rn(v.z - __half2float(h2));
    __half l3 = __float2half_rn(v.w - __half2float(h3));
    __half2 a;
    a.x = h0; a.y = h1; *reinterpret_cast<__half2*>(h + i) = a;
    a.x = h2; a.y = h3; *reinterpret_cast<__half2*>(h + i + 2) = a;
    a.x = l0; a.y = l1; *reinterpret_cast<__half2*>(l + i) = a;
    a.x = l2; a.y = l3; *reinterpret_cast<__half2*>(l + i + 2) = a;
}

// W [K=512, N=512] -> Wt hi/lo [N, K]
__global__ __launch_bounds__(256) void wsplit(const float* __restrict__ W,
                                              __half* __restrict__ Wth, __half* __restrict__ Wtl)
{
    __shared__ float t[32][33];
    const int n0 = blockIdx.x * 32, k0 = blockIdx.y * 32;
    const int tx = threadIdx.x & 31, ty = threadIdx.x >> 5;
    #pragma unroll
    for (int i = 0; i < 4; i++) {
        const int r = ty + i * 8;
        t[r][tx] = W[(size_t)(k0 + r) * HD + n0 + tx];
    }
    __syncthreads();
    #pragma unroll
    for (int i = 0; i < 4; i++) {
        const int r = ty + i * 8;          // n
        const float v = t[tx][r];
        __half h = __float2half_rn(v);
        __half l = __float2half_rn(v - __half2float(h));
        const size_t dst = (size_t)(n0 + r) * FT + k0 + tx;
        Wth[dst] = h;
        Wtl[dst] = l;
    }
}

// V hi/lo [B*T, H] -> Vt hi/lo [B][H][T]
__global__ __launch_bounds__(256) void transpose_v(const __half* __restrict__ Vh,
                                                   const __half* __restrict__ Vl,
                                                   __half* __restrict__ Vth, __half* __restrict__ Vtl)
{
    __shared__ __half th[32][33], tl[32][33];
    const int b = blockIdx.z;
    const int h0 = blockIdx.x * 32, s0 = blockIdx.y * 32;
    const int tx = threadIdx.x & 31, ty = threadIdx.x >> 5;
    #pragma unroll
    for (int i = 0; i < 4; i++) {
        const int r = ty + i * 8;
        const size_t src = ((size_t)b * TT + s0 + r) * HD + h0 + tx;
        th[r][tx] = Vh[src];
        tl[r][tx] = Vl[src];
    }
    __syncthreads();
    #pragma unroll
    for (int i = 0; i < 4; i++) {
        const int r = ty + i * 8;          // h
        const size_t dst = ((size_t)b * HD + h0 + r) * TT + s0 + tx;
        Vth[dst] = th[tx][r];
        Vtl[dst] = tl[tx][r];
    }
}

// softmax over rows of 2048; writes P as fp16 hi/lo
__global__ __launch_bounds__(256) void softmax_k(const float* __restrict__ S,
                                                 __half* __restrict__ Ph, __half* __restrict__ Pl)
{
    const size_t off = (size_t)blockIdx.x * TT;
    const int tid = threadIdx.x;
    const float* p = S + off + tid * 8;
    float v[8];
    float4 a = *reinterpret_cast<const float4*>(p);
    float4 b = *reinterpret_cast<const float4*>(p + 4);
    v[0] = a.x; v[1] = a.y; v[2] = a.z; v[3] = a.w;
    v[4] = b.x; v[5] = b.y; v[6] = b.z; v[7] = b.w;

    __shared__ float red[8];
    float m = v[0];
    #pragma unroll
    for (int i = 1; i < 8; i++) m = fmaxf(m, v[i]);
    #pragma unroll
    for (int o = 16; o > 0; o >>= 1) m = fmaxf(m, __shfl_xor_sync(0xffffffffu, m, o));
    if ((tid & 31) == 0) red[tid >> 5] = m;
    __syncthreads();
    float M = red[0];
    #pragma unroll
    for (int i = 1; i < 8; i++) M = fmaxf(M, red[i]);
    __syncthreads();

    float s = 0.f;
    #pragma unroll
    for (int i = 0; i < 8; i++) { v[i] = __expf(v[i] - M); s += v[i]; }
    #pragma unroll
    for (int o = 16; o > 0; o >>= 1) s += __shfl_xor_sync(0xffffffffu, s, o);
    if ((tid & 31) == 0) red[tid >> 5] = s;
    __syncthreads();
    float tot = 0.f;
    #pragma unroll
    for (int i = 0; i < 8; i++) tot += red[i];
    const float inv = __fdividef(1.0f, tot);

    __half* ph = Ph + off + tid * 8;
    __half* pl = Pl + off + tid * 8;
    #pragma unroll
    for (int i = 0; i < 8; i += 2) {
        float x0 = v[i] * inv, x1 = v[i + 1] * inv;
        __half h0 = __float2half_rn(x0), h1 = __float2half_rn(x1);
        __half l0 = __float2half_rn(x0 - __half2float(h0));
        __half l1 = __float2half_rn(x1 - __half2float(h1));
        __half2 t;
        t.x = h0; t.y = h1; *reinterpret_cast<__half2*>(ph + i) = t;
        t.x = l0; t.y = l1; *reinterpret_cast<__half2*>(pl + i) = t;
    }
}

// ---------------- launch ----------------
extern "C" void kernel_launch(void* const* d_in, const int* in_sizes, int n_in,
                              void* d_out, int out_size)
{
    const float* q  = (const float*)d_in[0];
    const float* k  = (const float*)d_in[1];
    const float* v  = (const float*)d_in[2];
    const float* Wq = (const float*)d_in[3];
    const float* bq = (const float*)d_in[4];
    const float* Wk = (const float*)d_in[5];
    const float* bk = (const float*)d_in[6];
    const float* Wv = (const float*)d_in[7];
    const float* bv = (const float*)d_in[8];
    float* out = (float*)d_out;

    __half *qh, *ql, *kh, *kl, *vh, *vl;
    __half *wqh, *wql, *wkh, *wkl, *wvh, *wvl;
    __half *Qh, *Ql, *Kh, *Kl, *Vh, *Vl, *Vth, *Vtl, *Ph, *Pl;
    float* S;
    cudaGetSymbolAddress((void**)&qh, g_qh);   cudaGetSymbolAddress((void**)&ql, g_ql);
    cudaGetSymbolAddress((void**)&kh, g_kh);   cudaGetSymbolAddress((void**)&kl, g_kl);
    cudaGetSymbolAddress((void**)&vh, g_vh);   cudaGetSymbolAddress((void**)&vl, g_vl);
    cudaGetSymbolAddress((void**)&wqh, g_Wqh); cudaGetSymbolAddress((void**)&wql, g_Wql);
    cudaGetSymbolAddress((void**)&wkh, g_Wkh); cudaGetSymbolAddress((void**)&wkl, g_Wkl);
    cudaGetSymbolAddress((void**)&wvh, g_Wvh); cudaGetSymbolAddress((void**)&wvl, g_Wvl);
    cudaGetSymbolAddress((void**)&Qh, g_Qh);   cudaGetSymbolAddress((void**)&Ql, g_Ql);
    cudaGetSymbolAddress((void**)&Kh, g_Kh);   cudaGetSymbolAddress((void**)&Kl, g_Kl);
    cudaGetSymbolAddress((void**)&Vh, g_Vh);   cudaGetSymbolAddress((void**)&Vl, g_Vl);
    cudaGetSymbolAddress((void**)&Vth, g_Vth); cudaGetSymbolAddress((void**)&Vtl, g_Vtl);
    cudaGetSymbolAddress((void**)&S, g_S);
    cudaGetSymbolAddress((void**)&Ph, g_Ph);   cudaGetSymbolAddress((void**)&Pl, g_Pl);

    cudaFuncSetAttribute(gemm_mma<0>, cudaFuncAttributeMaxDynamicSharedMemorySize, GEMM_SMEM);
    cudaFuncSetAttribute(gemm_mma<1>, cudaFuncAttributeMaxDynamicSharedMemorySize, GEMM_SMEM);

    // 1) split inputs
    fsplit<<<MTOT * FT / 1024, 256>>>(q, qh, ql);
    fsplit<<<MTOT * FT / 1024, 256>>>(k, kh, kl);
    fsplit<<<MTOT * FT / 1024, 256>>>(v, vh, vl);
    // 2) transpose+split weights
    wsplit<<<dim3(16, 16), 256>>>(Wq, wqh, wql);
    wsplit<<<dim3(16, 16), 256>>>(Wk, wkh, wkl);
    wsplit<<<dim3(16, 16), 256>>>(Wv, wvh, wvl);
    // 3) projections (scale 0.25 folded into Q)
    dim3 gp(HD / 128, MTOT / 128, 1);
    gemm_mma<0><<<gp, 256, GEMM_SMEM>>>(qh, ql, wqh, wql, FT, FT, 0, 0, FT,
                                        bq, 0.25f, nullptr, Qh, Ql, HD, 0);
    gemm_mma<0><<<gp, 256, GEMM_SMEM>>>(kh, kl, wkh, wkl, FT, FT, 0, 0, FT,
                                        bk, 1.0f, nullptr, Kh, Kl, HD, 0);
    gemm_mma<0><<<gp, 256, GEMM_SMEM>>>(vh, vl, wvh, wvl, FT, FT, 0, 0, FT,
                                        bv, 1.0f, nullptr, Vh, Vl, HD, 0);
    // 4) transpose V
    transpose_v<<<dim3(HD / 32, TT / 32, BZ), 256>>>(Vh, Vl, Vth, Vtl);
    // 5) energy S = (0.25 Q) K^T
    dim3 ge(TT / 128, TT / 128, BZ);
    gemm_mma<1><<<ge, 256, GEMM_SMEM>>>(Qh, Ql, Kh, Kl, HD, HD,
                                        (long)TT * HD, (long)TT * HD, HD,
                                        nullptr, 1.0f, S, nullptr, nullptr,
                                        TT, (long)TT * TT);
    // 6) softmax -> P hi/lo
    softmax_k<<<MTOT, 256>>>(S, Ph, Pl);
    // 7) out = P V
    dim3 go(HD / 128, TT / 128, BZ);
    gemm_mma<1><<<go, 256, GEMM_SMEM>>>(Ph, Pl, Vth, Vtl, TT, TT,
                                        (long)TT * TT, (long)HD * TT, TT,
                                        nullptr, 1.0f, out, nullptr, nullptr,
                                        HD, (long)TT * HD);
}

// round 8
// speedup vs baseline: 1.9380x; 1.2985x over previous
#include <cuda_runtime.h>
#include <cuda_fp16.h>
#include <stdint.h>

#define BZ 8
#define TT 2048
#define FT 512
#define HD 512
#define MTOT (BZ * TT)   // 16384

// ---------------- scratch (device globals; allocation-free) ----------------
__device__ __align__(16) __half g_qh[MTOT * FT], g_ql[MTOT * FT];
__device__ __align__(16) __half g_kh[MTOT * FT], g_kl[MTOT * FT];
__device__ __align__(16) __half g_vh[MTOT * FT], g_vl[MTOT * FT];
__device__ __align__(16) __half g_Wqh[FT * HD], g_Wql[FT * HD];
__device__ __align__(16) __half g_Wkh[FT * HD], g_Wkl[FT * HD];
__device__ __align__(16) __half g_Wvh[FT * HD], g_Wvl[FT * HD];
__device__ __align__(16) __half g_Qh[MTOT * HD], g_Ql[MTOT * HD];
__device__ __align__(16) __half g_Kh[MTOT * HD], g_Kl[MTOT * HD];
__device__ __align__(16) __half g_Vh[MTOT * HD], g_Vl[MTOT * HD];
__device__ __align__(16) __half g_Vth[(size_t)BZ * HD * TT], g_Vtl[(size_t)BZ * HD * TT];
__device__ __align__(16) float g_S[(size_t)BZ * TT * TT];
__device__ __align__(16) __half g_Ph[(size_t)BZ * TT * TT];

// ---------------- helpers ----------------
__device__ __forceinline__ uint32_t smem_u32(const void* p) {
    uint32_t a;
    asm("{ .reg .u64 t; cvta.to.shared.u64 t, %1; cvt.u32.u64 %0, t; }" : "=r"(a) : "l"(p));
    return a;
}

#define CP16(dst, src) \
    asm volatile("cp.async.cg.shared.global [%0], [%1], 16;" :: "r"(dst), "l"(src) : "memory")

#define LDSM4(r, addr) \
    asm volatile("ldmatrix.sync.aligned.m8n8.x4.shared.b16 {%0,%1,%2,%3}, [%4];" \
                 : "=r"((r)[0]), "=r"((r)[1]), "=r"((r)[2]), "=r"((r)[3]) : "r"(addr))

#define MMAF32(d, a, b0, b1) \
    asm volatile("mma.sync.aligned.m16n8k16.row.col.f32.f16.f16.f32 " \
                 "{%0,%1,%2,%3}, {%4,%5,%6,%7}, {%8,%9}, {%0,%1,%2,%3};" \
                 : "+f"((d)[0]), "+f"((d)[1]), "+f"((d)[2]), "+f"((d)[3]) \
                 : "r"((a)[0]), "r"((a)[1]), "r"((a)[2]), "r"((a)[3]), "r"(b0), "r"(b1))

// ---------------- warp-MMA GEMM ----------------
// D[m,n] = sum_k A[m,k]*B[n,k], fp16 split, f32 accumulate.
// TERMS=3: Ah*Bh + Ah*Bl + Al*Bh  (A split + B split)
// TERMS=2: Ah*Bh + Ah*Bl          (A plain fp16, B split; Al tile unused)
// K-chunk 32 (64B rows, SW64 swizzle), double-buffered, 64KB smem, 2 CTAs/SM.
static constexpr int TILE_B = 8192;             // 128 rows x 64 bytes
static constexpr int STAGE_B = 4 * TILE_B;      // Ah, Al, Bh, Bl = 32 KB
static constexpr int GEMM_SMEM = 2 * STAGE_B;   // 64 KB

__device__ __forceinline__ void load_tile(uint32_t dstbase, const __half* src, int ld, int tid)
{
    #pragma unroll
    for (int j = 0; j < 2; j++) {
        const int seg = tid + j * 256;          // 512 segs of 16B
        const int row = seg >> 2;               // 0..127
        const int colb = (seg & 3) * 16;        // 0..48
        const uint32_t off = (uint32_t)(row * 64 + colb);
        const uint32_t sw = off ^ ((off >> 3) & 0x30);
        CP16(dstbase + sw, (const char*)src + (long)row * ld * 2 + colb);
    }
}

template <int MODE, int TERMS>
__global__ __launch_bounds__(256, 2)
void gemm_mma(const __half* __restrict__ Ah, const __half* __restrict__ Al,
              const __half* __restrict__ Bh, const __half* __restrict__ Bl,
              int lda, int ldb, long sA, long sB, int K,
              const float* __restrict__ bias, float scale,
              float* __restrict__ outF, __half* __restrict__ outH, __half* __restrict__ outL,
              int ldo, long sO)
{
    extern __shared__ char smem[];
    const uint32_t sbase = smem_u32(smem);
    const int tid = threadIdx.x;
    const int wid = tid >> 5;
    const int L = tid & 31;
    const int bm = blockIdx.y * 128;
    const int bn = blockIdx.x * 128;
    const int wm = wid & 1;       // 0..1  (64 rows each)
    const int wn = wid >> 1;      // 0..3  (32 cols each)

    const __half* pAh = Ah + (long)blockIdx.z * sA + (long)bm * lda;
    const __half* pAl = Al + (long)blockIdx.z * sA + (long)bm * lda;
    const __half* pBh = Bh + (long)blockIdx.z * sB + (long)bn * ldb;
    const __half* pBl = Bl + (long)blockIdx.z * sB + (long)bn * ldb;

    const int lr = L & 15;
    const int lc = (L >> 4) * 16;
    uint32_t aoffu[4], apat[4], boffu[2], bpat[2];
    #pragma unroll
    for (int mt = 0; mt < 4; mt++) {
        const uint32_t off = (uint32_t)((wm * 64 + mt * 16 + lr) * 64 + lc);
        aoffu[mt] = off;
        apat[mt] = (off >> 3) & 0x30;
    }
    #pragma unroll
    for (int ng = 0; ng < 2; ng++) {
        const uint32_t off = (uint32_t)((wn * 32 + ng * 16 + lr) * 64 + lc);
        boffu[ng] = off;
        bpat[ng] = (off >> 3) & 0x30;
    }

    float acc[4][4][4];
    #pragma unroll
    for (int mt = 0; mt < 4; mt++)
        #pragma unroll
        for (int nt = 0; nt < 4; nt++)
            #pragma unroll
            for (int r = 0; r < 4; r++)
                acc[mt][nt][r] = 0.0f;

    const int nchunk = K / 32;

    load_tile(sbase + 0 * TILE_B, pAh, lda, tid);
    if (TERMS == 3) load_tile(sbase + 1 * TILE_B, pAl, lda, tid);
    load_tile(sbase + 2 * TILE_B, pBh, ldb, tid);
    load_tile(sbase + 3 * TILE_B, pBl, ldb, tid);
    asm volatile("cp.async.commit_group;" ::: "memory");

    for (int ck = 0; ck < nchunk; ck++) {
        const int buf = ck & 1;
        if (ck + 1 < nchunk) {
            const int k0 = (ck + 1) * 32;
            const uint32_t db = sbase + (buf ^ 1) * STAGE_B;
            load_tile(db + 0 * TILE_B, pAh + k0, lda, tid);
            if (TERMS == 3) load_tile(db + 1 * TILE_B, pAl + k0, lda, tid);
            load_tile(db + 2 * TILE_B, pBh + k0, ldb, tid);
            load_tile(db + 3 * TILE_B, pBl + k0, ldb, tid);
            asm volatile("cp.async.commit_group;" ::: "memory");
            asm volatile("cp.async.wait_group 1;" ::: "memory");
        } else {
            asm volatile("cp.async.wait_group 0;" ::: "memory");
        }
        __syncthreads();

        const uint32_t cb = sbase + buf * STAGE_B;
        #pragma unroll
        for (int kk = 0; kk < 2; kk++) {
            uint32_t bh[2][4], bl[2][4];
            #pragma unroll
            for (int ng = 0; ng < 2; ng++) {
                const uint32_t sw = (boffu[ng] + kk * 32) ^ bpat[ng];
                LDSM4(bh[ng], cb + 2 * TILE_B + sw);
                LDSM4(bl[ng], cb + 3 * TILE_B + sw);
            }
            #pragma unroll
            for (int mt = 0; mt < 4; mt++) {
                uint32_t ah[4], al[4];
                const uint32_t sw = (aoffu[mt] + kk * 32) ^ apat[mt];
                LDSM4(ah, cb + 0 * TILE_B + sw);
                if (TERMS == 3) LDSM4(al, cb + 1 * TILE_B + sw);
                #pragma unroll
                for (int nt = 0; nt < 4; nt++) {
                    const int ng = nt >> 1, h = nt & 1;
                    const uint32_t b0h = bh[ng][h], b1h = bh[ng][h + 2];
                    const uint32_t b0l = bl[ng][h], b1l = bl[ng][h + 2];
                    MMAF32(acc[mt][nt], ah, b0h, b1h);
                    MMAF32(acc[mt][nt], ah, b0l, b1l);
                    if (TERMS == 3) MMAF32(acc[mt][nt], al, b0h, b1h);
                }
            }
        }
        __syncthreads();
    }

    // epilogue
    const int r0 = bm + wm * 64 + (L >> 2);
    const int c0 = bn + wn * 32 + (L & 3) * 2;
    #pragma unroll
    for (int mt = 0; mt < 4; mt++) {
        #pragma unroll
        for (int nt = 0; nt < 4; nt++) {
            const int row = r0 + mt * 16;
            const int col = c0 + nt * 8;
            if (MODE == 1) {
                float* po = outF + (size_t)blockIdx.z * sO;
                *reinterpret_cast<float2*>(po + (size_t)row * ldo + col) =
                    make_float2(acc[mt][nt][0], acc[mt][nt][1]);
                *reinterpret_cast<float2*>(po + (size_t)(row + 8) * ldo + col) =
                    make_float2(acc[mt][nt][2], acc[mt][nt][3]);
            } else {
                const float b0 = bias[col], b1 = bias[col + 1];
                float x0 = (acc[mt][nt][0] + b0) * scale;
                float x1 = (acc[mt][nt][1] + b1) * scale;
                float x2 = (acc[mt][nt][2] + b0) * scale;
                float x3 = (acc[mt][nt][3] + b1) * scale;
                __half h0 = __float2half_rn(x0), h1 = __float2half_rn(x1);
                __half h2 = __float2half_rn(x2), h3 = __float2half_rn(x3);
                __half l0 = __float2half_rn(x0 - __half2float(h0));
                __half l1 = __float2half_rn(x1 - __half2float(h1));
                __half l2 = __float2half_rn(x2 - __half2float(h2));
                __half l3 = __float2half_rn(x3 - __half2float(h3));
                __half2 t;
                t.x = h0; t.y = h1;
                *reinterpret_cast<__half2*>(outH + (size_t)row * ldo + col) = t;
                t.x = h2; t.y = h3;
                *reinterpret_cast<__half2*>(outH + (size_t)(row + 8) * ldo + col) = t;
                t.x = l0; t.y = l1;
                *reinterpret_cast<__half2*>(outL + (size_t)row * ldo + col) = t;
                t.x = l2; t.y = l3;
                *reinterpret_cast<__half2*>(outL + (size_t)(row + 8) * ldo + col) = t;
            }
        }
    }
}

// ---------------- small kernels ----------------
__global__ __launch_bounds__(256) void fsplit(const float* __restrict__ x,
                                              __half* __restrict__ h, __half* __restrict__ l)
{
    const int i = (blockIdx.x * 256 + threadIdx.x) * 4;
    float4 v = *reinterpret_cast<const float4*>(x + i);
    __half h0 = __float2half_rn(v.x), h1 = __float2half_rn(v.y);
    __half h2 = __float2half_rn(v.z), h3 = __float2half_rn(v.w);
    __half l0 = __float2half_rn(v.x - __half2float(h0));
    __half l1 = __float2half_rn(v.y - __half2float(h1));
    __half l2 = __float2half_rn(v.z - __half2float(h2));
    __half l3 = __float2half_rn(v.w - __half2float(h3));
    __half2 a;
    a.x = h0; a.y = h1; *reinterpret_cast<__half2*>(h + i) = a;
    a.x = h2; a.y = h3; *reinterpret_cast<__half2*>(h + i + 2) = a;
    a.x = l0; a.y = l1; *reinterpret_cast<__half2*>(l + i) = a;
    a.x = l2; a.y = l3; *reinterpret_cast<__half2*>(l + i + 2) = a;
}

// W [K=512, N=512] -> Wt hi/lo [N, K]
__global__ __launch_bounds__(256) void wsplit(const float* __restrict__ W,
                                              __half* __restrict__ Wth, __half* __restrict__ Wtl)
{
    __shared__ float t[32][33];
    const int n0 = blockIdx.x * 32, k0 = blockIdx.y * 32;
    const int tx = threadIdx.x & 31, ty = threadIdx.x >> 5;
    #pragma unroll
    for (int i = 0; i < 4; i++) {
        const int r = ty + i * 8;
        t[r][tx] = W[(size_t)(k0 + r) * HD + n0 + tx];
    }
    __syncthreads();
    #pragma unroll
    for (int i = 0; i < 4; i++) {
        const int r = ty + i * 8;          // n
        const float v = t[tx][r];
        __half h = __float2half_rn(v);
        __half l = __float2half_rn(v - __half2float(h));
        const size_t dst = (size_t)(n0 + r) * FT + k0 + tx;
        Wth[dst] = h;
        Wtl[dst] = l;
    }
}

// V hi/lo [B*T, H] -> Vt hi/lo [B][H][T]
__global__ __launch_bounds__(256) void transpose_v(const __half* __restrict__ Vh,
                                                   const __half* __restrict__ Vl,
                                                   __half* __restrict__ Vth, __half* __restrict__ Vtl)
{
    __shared__ __half th[32][33], tl[32][33];
    const int b = blockIdx.z;
    const int h0 = blockIdx.x * 32, s0 = blockIdx.y * 32;
    const int tx = threadIdx.x & 31, ty = threadIdx.x >> 5;
    #pragma unroll
    for (int i = 0; i < 4; i++) {
        const int r = ty + i * 8;
        const size_t src = ((size_t)b * TT + s0 + r) * HD + h0 + tx;
        th[r][tx] = Vh[src];
        tl[r][tx] = Vl[src];
    }
    __syncthreads();
    #pragma unroll
    for (int i = 0; i < 4; i++) {
        const int r = ty + i * 8;          // h
        const size_t dst = ((size_t)b * HD + h0 + r) * TT + s0 + tx;
        Vth[dst] = th[tx][r];
        Vtl[dst] = tl[tx][r];
    }
}

// softmax over rows of 2048; writes P as plain fp16 (PV uses 2-term split on V only)
__global__ __launch_bounds__(256) void softmax_k(const float* __restrict__ S,
                                                 __half* __restrict__ Ph)
{
    const size_t off = (size_t)blockIdx.x * TT;
    const int tid = threadIdx.x;
    const float* p = S + off + tid * 8;
    float v[8];
    float4 a = *reinterpret_cast<const float4*>(p);
    float4 b = *reinterpret_cast<const float4*>(p + 4);
    v[0] = a.x; v[1] = a.y; v[2] = a.z; v[3] = a.w;
    v[4] = b.x; v[5] = b.y; v[6] = b.z; v[7] = b.w;

    __shared__ float red[8];
    float m = v[0];
    #pragma unroll
    for (int i = 1; i < 8; i++) m = fmaxf(m, v[i]);
    #pragma unroll
    for (int o = 16; o > 0; o >>= 1) m = fmaxf(m, __shfl_xor_sync(0xffffffffu, m, o));
    if ((tid & 31) == 0) red[tid >> 5] = m;
    __syncthreads();
    float M = red[0];
    #pragma unroll
    for (int i = 1; i < 8; i++) M = fmaxf(M, red[i]);
    __syncthreads();

    float s = 0.f;
    #pragma unroll
    for (int i = 0; i < 8; i++) { v[i] = __expf(v[i] - M); s += v[i]; }
    #pragma unroll
    for (int o = 16; o > 0; o >>= 1) s += __shfl_xor_sync(0xffffffffu, s, o);
    if ((tid & 31) == 0) red[tid >> 5] = s;
    __syncthreads();
    float tot = 0.f;
    #pragma unroll
    for (int i = 0; i < 8; i++) tot += red[i];
    const float inv = __fdividef(1.0f, tot);

    __half* ph = Ph + off + tid * 8;
    #pragma unroll
    for (int i = 0; i < 8; i += 2) {
        __half2 t;
        t.x = __float2half_rn(v[i] * inv);
        t.y = __float2half_rn(v[i + 1] * inv);
        *reinterpret_cast<__half2*>(ph + i) = t;
    }
}

// ---------------- launch ----------------
extern "C" void kernel_launch(void* const* d_in, const int* in_sizes, int n_in,
                              void* d_out, int out_size)
{
    const float* q  = (const float*)d_in[0];
    const float* k  = (const float*)d_in[1];
    const float* v  = (const float*)d_in[2];
    const float* Wq = (const float*)d_in[3];
    const float* bq = (const float*)d_in[4];
    const float* Wk = (const float*)d_in[5];
    const float* bk = (const float*)d_in[6];
    const float* Wv = (const float*)d_in[7];
    const float* bv = (const float*)d_in[8];
    float* out = (float*)d_out;

    __half *qh, *ql, *kh, *kl, *vh, *vl;
    __half *wqh, *wql, *wkh, *wkl, *wvh, *wvl;
    __half *Qh, *Ql, *Kh, *Kl, *Vh, *Vl, *Vth, *Vtl, *Ph;
    float* S;
    cudaGetSymbolAddress((void**)&qh, g_qh);   cudaGetSymbolAddress((void**)&ql, g_ql);
    cudaGetSymbolAddress((void**)&kh, g_kh);   cudaGetSymbolAddress((void**)&kl, g_kl);
    cudaGetSymbolAddress((void**)&vh, g_vh);   cudaGetSymbolAddress((void**)&vl, g_vl);
    cudaGetSymbolAddress((void**)&wqh, g_Wqh); cudaGetSymbolAddress((void**)&wql, g_Wql);
    cudaGetSymbolAddress((void**)&wkh, g_Wkh); cudaGetSymbolAddress((void**)&wkl, g_Wkl);
    cudaGetSymbolAddress((void**)&wvh, g_Wvh); cudaGetSymbolAddress((void**)&wvl, g_Wvl);
    cudaGetSymbolAddress((void**)&Qh, g_Qh);   cudaGetSymbolAddress((void**)&Ql, g_Ql);
    cudaGetSymbolAddress((void**)&Kh, g_Kh);   cudaGetSymbolAddress((void**)&Kl, g_Kl);
    cudaGetSymbolAddress((void**)&Vh, g_Vh);   cudaGetSymbolAddress((void**)&Vl, g_Vl);
    cudaGetSymbolAddress((void**)&Vth, g_Vth); cudaGetSymbolAddress((void**)&Vtl, g_Vtl);
    cudaGetSymbolAddress((void**)&S, g_S);
    cudaGetSymbolAddress((void**)&Ph, g_Ph);

    cudaFuncSetAttribute((const void*)gemm_mma<0, 3>, cudaFuncAttributeMaxDynamicSharedMemorySize, GEMM_SMEM);
    cudaFuncSetAttribute((const void*)gemm_mma<1, 3>, cudaFuncAttributeMaxDynamicSharedMemorySize, GEMM_SMEM);
    cudaFuncSetAttribute((const void*)gemm_mma<1, 2>, cudaFuncAttributeMaxDynamicSharedMemorySize, GEMM_SMEM);

    // 1) split inputs
    fsplit<<<MTOT * FT / 1024, 256>>>(q, qh, ql);
    fsplit<<<MTOT * FT / 1024, 256>>>(k, kh, kl);
    fsplit<<<MTOT * FT / 1024, 256>>>(v, vh, vl);
    // 2) transpose+split weights
    wsplit<<<dim3(16, 16), 256>>>(Wq, wqh, wql);
    wsplit<<<dim3(16, 16), 256>>>(Wk, wkh, wkl);
    wsplit<<<dim3(16, 16), 256>>>(Wv, wvh, wvl);
    // 3) projections, 3-term (scale 0.25 folded into Q)
    dim3 gp(HD / 128, MTOT / 128, 1);
    gemm_mma<0, 3><<<gp, 256, GEMM_SMEM>>>(qh, ql, wqh, wql, FT, FT, 0, 0, FT,
                                           bq, 0.25f, nullptr, Qh, Ql, HD, 0);
    gemm_mma<0, 3><<<gp, 256, GEMM_SMEM>>>(kh, kl, wkh, wkl, FT, FT, 0, 0, FT,
                                           bk, 1.0f, nullptr, Kh, Kl, HD, 0);
    gemm_mma<0, 3><<<gp, 256, GEMM_SMEM>>>(vh, vl, wvh, wvl, FT, FT, 0, 0, FT,
                                           bv, 1.0f, nullptr, Vh, Vl, HD, 0);
    // 4) transpose V
    transpose_v<<<dim3(HD / 32, TT / 32, BZ), 256>>>(Vh, Vl, Vth, Vtl);
    // 5) energy S = (0.25 Q) K^T, 3-term
    dim3 ge(TT / 128, TT / 128, BZ);
    gemm_mma<1, 3><<<ge, 256, GEMM_SMEM>>>(Qh, Ql, Kh, Kl, HD, HD,
                                           (long)TT * HD, (long)TT * HD, HD,
                                           nullptr, 1.0f, S, nullptr, nullptr,
                                           TT, (long)TT * TT);
    // 6) softmax -> P plain fp16
    softmax_k<<<MTOT, 256>>>(S, Ph);
    // 7) out = P V, 2-term (P plain, V split)
    dim3 go(HD / 128, TT / 128, BZ);
    gemm_mma<1, 2><<<go, 256, GEMM_SMEM>>>(Ph, Ph, Vth, Vtl, TT, TT,
                                           (long)TT * TT, (long)HD * TT, TT,
                                           nullptr, 1.0f, out, nullptr, nullptr,
                                           HD, (long)TT * HD);
}